// round 9
// baseline (speedup 1.0000x reference)
#include <cuda_runtime.h>
#include <cstdint>
#include <cstddef>

// Problem constants
#define BB 2
#define NN 512
#define KK 128
#define EE 768

// Output layout (concatenated, fp32): edge_feature | merge | delta_pos
static const size_t EF_ELEMS  = (size_t)BB * NN * NN * KK;   // 67,108,864
static const size_t MERGE_OFF = EF_ELEMS;                    // 67,108,864
static const size_t DP_OFF    = EF_ELEMS + (size_t)BB*NN*EE; // 67,895,296

// Scratch (device globals only — no allocation allowed)
__device__ __align__(16) float g_mk[KK];    // means * k1  (for u = fma(x, k1, -mk))
__device__ __align__(16) float g_k1[KK];    // (1/(|std|+0.01)) * sqrt(0.5*log2(e))
__device__ __align__(16) float g_coef[KK];  // (1/(|std|+0.01)) / sqrt(2*PI)
__device__ __align__(16) float g_t2[BB * KK];   // 2 * t_enc(time_pos[b])
__device__ __align__(16) float g_t02[KK];       // 2 * t_enc(0)
__device__ float g_sum[BB * NN * KK];           // sum over j of edge_feature

__device__ __forceinline__ float ex2f(float x) {
    float r; asm("ex2.approx.ftz.f32 %0, %1;" : "=f"(r) : "f"(x)); return r;
}

// ---------------------------------------------------------------------------
// Kernel P (fused MLP prep): 3 blocks (one per row r in {t0, t1, 0}),
// 1024 threads. Warp w owns outputs k = 4w..4w+3; lane l sums over
// j in {l, l+32, l+64, l+96} -> 16 independent LDGs per lane per layer
// (one memory-latency round per layer). Block 0 also writes gaussian consts.
// ---------------------------------------------------------------------------
__global__ __launch_bounds__(1024) void prep_mlp(
        const float* __restrict__ W1, const float* __restrict__ b1,
        const float* __restrict__ W2, const float* __restrict__ b2,
        const int*   __restrict__ tpos,
        const float* __restrict__ means, const float* __restrict__ stds) {
    const int r = blockIdx.x;
    const int w = threadIdx.x >> 5, l = threadIdx.x & 31;
    __shared__ float sh[KK];

    if (r == 0 && threadIdx.x < KK) {
        const int k = threadIdx.x;
        float sd = fabsf(__ldg(&stds[k])) + 0.01f;
        float is = 1.0f / sd;
        float k1 = is * 0.8493218002880191f;                // sqrt(0.5 * log2(e))
        g_k1[k]   = k1;
        g_mk[k]   = __ldg(&means[k]) * k1;
        g_coef[k] = is * (1.0f / sqrtf(2.0f * 3.14159f));   // ref's PI constant
    }

    const float t = (r < 2) ? (float)__ldg(&tpos[r]) : 0.0f;

    // ---- layer 1 ----
    float acc[4] = {0.f, 0.f, 0.f, 0.f};
    #pragma unroll
    for (int seg = 0; seg < 4; seg++) {
        int j = l + 32 * seg;
        int h = (j < 64) ? j : (j - 64);
        float freq = expf(-9.210340371976184f * (float)h / 64.0f);
        float arg = t * freq;
        float e = (j < 64) ? cosf(arg) : sinf(arg);
        #pragma unroll
        for (int q = 0; q < 4; q++)
            acc[q] = fmaf(e, __ldg(&W1[j * KK + 4 * w + q]), acc[q]);
    }
    #pragma unroll
    for (int q = 0; q < 4; q++)
        #pragma unroll
        for (int o = 16; o > 0; o >>= 1)
            acc[q] += __shfl_xor_sync(0xffffffffu, acc[q], o);
    if (l == 0) {
        #pragma unroll
        for (int q = 0; q < 4; q++) {
            int k = 4 * w + q;
            float hv = acc[q] + __ldg(&b1[k]);
            sh[k] = hv / (1.0f + expf(-hv));   // SiLU
        }
    }
    __syncthreads();

    // ---- layer 2 ----
    float acc2[4] = {0.f, 0.f, 0.f, 0.f};
    #pragma unroll
    for (int seg = 0; seg < 4; seg++) {
        int j = l + 32 * seg;
        float e = sh[j];
        #pragma unroll
        for (int q = 0; q < 4; q++)
            acc2[q] = fmaf(e, __ldg(&W2[j * KK + 4 * w + q]), acc2[q]);
    }
    #pragma unroll
    for (int q = 0; q < 4; q++)
        #pragma unroll
        for (int o = 16; o > 0; o >>= 1)
            acc2[q] += __shfl_xor_sync(0xffffffffu, acc2[q], o);
    if (l == 0) {
        #pragma unroll
        for (int q = 0; q < 4; q++) {
            int k = 4 * w + q;
            float o2 = 2.0f * (acc2[q] + __ldg(&b2[k]));
            if (r < 2) g_t2[r * KK + k] = o2;
            else       g_t02[k]         = o2;
        }
    }
}

// ---------------------------------------------------------------------------
// Kernel B: main edge kernel. 512 blocks; block handles 2 consecutive i-rows
// of one batch b (single full wave at 5 blocks/SM -> no tail wave).
// Per row: 8 warps, warp w owns j in [w*64,(w+1)*64) in two 32-wide chunks:
//   - scalar phase lane-parallel over j (dist, 1/dist, x = mul*dist+bias)
//   - broadcast phase: per j, each lane computes 4 contiguous k, stores float4
//     with a warp-UNIFORM branch that skips all math for padded j (store zeros)
// ---------------------------------------------------------------------------
__global__ __launch_bounds__(256) void edge_kernel(
        const float* __restrict__ pos,
        const int*   __restrict__ nte,
        const int*   __restrict__ pad,
        const int*   __restrict__ maa,
        const int*   __restrict__ mpos,
        const float* __restrict__ mul_w,
        const float* __restrict__ bias_w,
        float* __restrict__ ef,
        float* __restrict__ dp) {
    const int b  = blockIdx.x >> 8;            // 512 blocks: b = hi bit
    const int i0 = (blockIdx.x & 255) * 2;     // 2 rows per block
    const int tid = threadIdx.x, wid = tid >> 5, lid = tid & 31;

    __shared__ float spx[NN], spy[NN], spz[NN];
    __shared__ int   sfl[NN];
    __shared__ float sred[KK];

    for (int idx = tid; idx < NN; idx += 256) {
        int g = b * NN + idx;
        spx[idx] = pos[g * 3 + 0];
        spy[idx] = pos[g * 3 + 1];
        spz[idx] = pos[g * 3 + 2];
        sfl[idx] = (pad[g] ? 1 : 0) | (mpos[g] ? 2 : 0) | (maa[g] ? 4 : 0);
    }

    // per-lane gaussian constants for k = 4*lid .. 4*lid+3 (b-dependent tv4)
    const float4 mk4 = *(const float4*)&g_mk[4 * lid];
    const float4 k4  = *(const float4*)&g_k1[4 * lid];
    const float4 c4  = *(const float4*)&g_coef[4 * lid];
    const float4 tv4 = *(const float4*)&g_t2[b * KK + 4 * lid];
    const float4 t04 = *(const float4*)&g_t02[4 * lid];

    const int2* ntep = (const int2*)nte;

    for (int ii = 0; ii < 2; ii++) {
        const int i = i0 + ii;
        if (tid < KK) sred[tid] = 0.0f;
        __syncthreads();

        const float pix = spx[i], piy = spy[i], piz = spz[i];
        const int fi = sfl[i];
        const bool maa_i = (fi & 4) != 0;
        const bool mp_i  = (fi & 2) != 0;
        const size_t row = (size_t)(b * NN + i) * NN;

        float a0 = 0.f, a1 = 0.f, a2 = 0.f, a3 = 0.f;

        for (int jb = wid * 64; jb < wid * 64 + 64; jb += 32) {
            const int j = jb + lid;
            // ---- scalar phase (lane-parallel over j) ----
            float dx = spx[j] - pix, dy = spy[j] - piy, dz = spz[j] - piz;
            float d2 = fmaf(dx, dx, fmaf(dy, dy, dz * dz));
            float dist = __fsqrt_rn(d2);
            float inv = __fdividef(1.0f, dist + 1e-5f);
            size_t dpb = (row + j) * 3;
            __stcs(dp + dpb + 0, dx * inv);
            __stcs(dp + dpb + 1, dy * inv);
            __stcs(dp + dpb + 2, dz * inv);

            int2 v = __ldg(&ntep[row + j]);
            int f = sfl[j];
            int e0 = maa_i    ? 0 : v.x;
            int e1 = (f & 4)  ? 0 : v.y;
            float mul = __ldg(&mul_w[e0])  + __ldg(&mul_w[e1]);
            float bia = __ldg(&bias_w[e0]) + __ldg(&bias_w[e1]);
            float x = fmaf(mul, dist, bia);

            unsigned pmask = __ballot_sync(0xffffffffu, (f & 1) != 0);
            unsigned smask = __ballot_sync(0xffffffffu, mp_i || ((f & 2) != 0));

            // ---- broadcast phase: per j, 128 k across warp ----
            #pragma unroll 4
            for (int t = 0; t < 32; t++) {
                float xt = __shfl_sync(0xffffffffu, x, t);
                float4* op = (float4*)(ef + (row + jb + t) * KK) + lid;
                if ((pmask >> t) & 1u) {           // warp-uniform: padded j
                    __stcs(op, make_float4(0.f, 0.f, 0.f, 0.f));
                } else {
                    const bool sel = (smask >> t) & 1u;
                    float u0 = fmaf(xt, k4.x, -mk4.x);
                    float u1 = fmaf(xt, k4.y, -mk4.y);
                    float u2 = fmaf(xt, k4.z, -mk4.z);
                    float u3 = fmaf(xt, k4.w, -mk4.w);
                    float v0 = fmaf(c4.x, ex2f(-u0 * u0), sel ? tv4.x : t04.x);
                    float v1 = fmaf(c4.y, ex2f(-u1 * u1), sel ? tv4.y : t04.y);
                    float v2 = fmaf(c4.z, ex2f(-u2 * u2), sel ? tv4.z : t04.z);
                    float v3 = fmaf(c4.w, ex2f(-u3 * u3), sel ? tv4.w : t04.w);
                    a0 += v0; a1 += v1; a2 += v2; a3 += v3;
                    __stcs(op, make_float4(v0, v1, v2, v3));
                }
            }
        }

        atomicAdd(&sred[4 * lid + 0], a0);
        atomicAdd(&sred[4 * lid + 1], a1);
        atomicAdd(&sred[4 * lid + 2], a2);
        atomicAdd(&sred[4 * lid + 3], a3);
        __syncthreads();
        if (tid < KK) g_sum[(size_t)(b * NN + i) * KK + tid] = sred[tid];
        __syncthreads();
    }
}

// ---------------------------------------------------------------------------
// Kernel C: merge = sum_edge @ proj_w + proj_b, zero padded i-rows.
// grid = (128 row-blocks) x (3 E-slices). Each block: 8 rows x 256 E-cols.
// smem: st[k] = {rows 0..3, rows 4..7} as two float4 (16B-aligned ->
// broadcast LDS.128). Inner loop per k: 1 LDG + 2 LDS.128 + 8 FMA, unroll 8.
// ---------------------------------------------------------------------------
__global__ __launch_bounds__(256) void proj_kernel(
        const float* __restrict__ W,
        const float* __restrict__ bias,
        const int*   __restrict__ pad,
        float* __restrict__ merge) {
    const int r0 = blockIdx.x * 8;
    const int e0 = blockIdx.y * 256 + threadIdx.x;
    __shared__ float4 st[KK][2];     // st[k][0] = rows 0-3, st[k][1] = rows 4-7
    for (int idx = threadIdx.x; idx < 8 * KK; idx += 256) {
        int r = idx >> 7, k = idx & (KK - 1);     // coalesced g_sum read
        ((float*)st)[k * 8 + r] = g_sum[(r0 + r) * KK + k];
    }
    __syncthreads();

    float acc[8];
    #pragma unroll
    for (int r = 0; r < 8; r++) acc[r] = 0.f;

    #pragma unroll 8
    for (int k = 0; k < KK; k++) {
        float w0 = __ldg(&W[k * EE + e0]);
        float4 s0 = st[k][0];
        float4 s1 = st[k][1];
        acc[0] = fmaf(s0.x, w0, acc[0]);
        acc[1] = fmaf(s0.y, w0, acc[1]);
        acc[2] = fmaf(s0.z, w0, acc[2]);
        acc[3] = fmaf(s0.w, w0, acc[3]);
        acc[4] = fmaf(s1.x, w0, acc[4]);
        acc[5] = fmaf(s1.y, w0, acc[5]);
        acc[6] = fmaf(s1.z, w0, acc[6]);
        acc[7] = fmaf(s1.w, w0, acc[7]);
    }
    float b0 = __ldg(&bias[e0]);
    #pragma unroll
    for (int r = 0; r < 8; r++) {
        int rr = r0 + r;
        bool p = pad[rr] != 0;
        merge[(size_t)rr * EE + e0] = p ? 0.f : acc[r] + b0;
    }
}

// ---------------------------------------------------------------------------
extern "C" void kernel_launch(void* const* d_in, const int* in_sizes, int n_in,
                              void* d_out, int out_size) {
    const float* pos    = (const float*)d_in[0];
    const int*   nte    = (const int*)  d_in[1];
    const int*   pad    = (const int*)  d_in[2];
    const int*   maa    = (const int*)  d_in[3];
    const int*   mpos   = (const int*)  d_in[4];
    const int*   tpos   = (const int*)  d_in[5];
    const float* means  = (const float*)d_in[6];
    const float* stds   = (const float*)d_in[7];
    const float* mul_w  = (const float*)d_in[8];
    const float* bias_w = (const float*)d_in[9];
    const float* proj_w = (const float*)d_in[10];
    const float* proj_b = (const float*)d_in[11];
    const float* t_w1   = (const float*)d_in[12];
    const float* t_b1   = (const float*)d_in[13];
    const float* t_w2   = (const float*)d_in[14];
    const float* t_b2   = (const float*)d_in[15];
    float* out = (float*)d_out;

    prep_mlp<<<3, 1024>>>(t_w1, t_b1, t_w2, t_b2, tpos, means, stds);
    edge_kernel<<<BB * NN / 2, 256>>>(pos, nte, pad, maa, mpos, mul_w, bias_w,
                                      out, out + DP_OFF);
    proj_kernel<<<dim3((BB * NN) / 8, 3), 256>>>(proj_w, proj_b, pad, out + MERGE_OFF);
}

// round 10
// speedup vs baseline: 1.1739x; 1.1739x over previous
#include <cuda_runtime.h>
#include <cstdint>
#include <cstddef>

// Problem constants
#define BB 2
#define NN 512
#define KK 128
#define EE 768

// Output layout (concatenated, fp32): edge_feature | merge | delta_pos
static const size_t EF_ELEMS  = (size_t)BB * NN * NN * KK;   // 67,108,864
static const size_t MERGE_OFF = EF_ELEMS;                    // 67,108,864
static const size_t DP_OFF    = EF_ELEMS + (size_t)BB*NN*EE; // 67,895,296

// Scratch (device globals only — no allocation allowed)
__device__ __align__(16) float g_mk[KK];    // means * k1  (for u = fma(x, k1, -mk))
__device__ __align__(16) float g_k1[KK];    // (1/(|std|+0.01)) * sqrt(0.5*log2(e))
__device__ __align__(16) float g_coef[KK];  // (1/(|std|+0.01)) / sqrt(2*PI)
__device__ __align__(16) float g_t2[BB * KK];   // 2 * t_enc(time_pos[b])
__device__ __align__(16) float g_t02[KK];       // 2 * t_enc(0)
__device__ __align__(16) float g_h[3 * KK];     // hidden after SiLU
__device__ float g_sum[BB * NN * KK];           // sum over j of edge_feature

__device__ __forceinline__ float ex2f(float x) {
    float r; asm("ex2.approx.ftz.f32 %0, %1;" : "=f"(r) : "f"(x)); return r;
}

// ---------------------------------------------------------------------------
// Kernel P1: layer-1 of timestep MLP. 12 blocks x 1024 thr = 384 warps,
// one warp per output (r,k); r in {t0, t1, 0}, k in [0,128).
// Each lane computes its 4 sinusoidal-embedding values inline,
// loads 4 W1 elements (independent -> single latency round), shfl-reduce.
// ---------------------------------------------------------------------------
__global__ __launch_bounds__(1024) void prep1(const float* __restrict__ W1,
                                              const float* __restrict__ b1,
                                              const int*   __restrict__ tpos) {
    const int w = blockIdx.x * 32 + (threadIdx.x >> 5);   // 0..383
    const int l = threadIdx.x & 31;
    const int r = w >> 7, k = w & (KK - 1);
    const float t = (r < 2) ? (float)__ldg(&tpos[r]) : 0.0f;

    float s = 0.0f;
    #pragma unroll
    for (int sgl = 0; sgl < 4; sgl++) {
        int j = l + 32 * sgl;
        int h = (j < 64) ? j : (j - 64);
        float freq = expf(-9.210340371976184f * (float)h / 64.0f);
        float arg = t * freq;
        float e = (j < 64) ? cosf(arg) : sinf(arg);
        s = fmaf(e, __ldg(&W1[j * KK + k]), s);
    }
    #pragma unroll
    for (int o = 16; o > 0; o >>= 1) s += __shfl_xor_sync(0xffffffffu, s, o);
    if (l == 0) {
        float hv = s + __ldg(&b1[k]);
        hv = hv / (1.0f + expf(-hv));     // SiLU
        g_h[r * KK + k] = hv;
    }
}

// ---------------------------------------------------------------------------
// Kernel P2: layer-2 of timestep MLP (same shape) + gaussian constants.
// ---------------------------------------------------------------------------
__global__ __launch_bounds__(1024) void prep2(const float* __restrict__ W2,
                                              const float* __restrict__ b2,
                                              const float* __restrict__ means,
                                              const float* __restrict__ stds) {
    if (blockIdx.x == 0 && threadIdx.x < KK) {
        const int k = threadIdx.x;
        float sd = fabsf(__ldg(&stds[k])) + 0.01f;
        float is = 1.0f / sd;
        float k1 = is * 0.8493218002880191f;                // sqrt(0.5 * log2(e))
        g_k1[k]   = k1;
        g_mk[k]   = __ldg(&means[k]) * k1;
        g_coef[k] = is * (1.0f / sqrtf(2.0f * 3.14159f));   // ref's PI constant
    }
    const int w = blockIdx.x * 32 + (threadIdx.x >> 5);
    const int l = threadIdx.x & 31;
    const int r = w >> 7, k = w & (KK - 1);
    float s = 0.0f;
    #pragma unroll
    for (int sgl = 0; sgl < 4; sgl++) {
        int j = l + 32 * sgl;
        s = fmaf(__ldg(&g_h[r * KK + j]), __ldg(&W2[j * KK + k]), s);
    }
    #pragma unroll
    for (int o = 16; o > 0; o >>= 1) s += __shfl_xor_sync(0xffffffffu, s, o);
    if (l == 0) {
        float o2 = 2.0f * (s + __ldg(&b2[k]));
        if (r < 2) g_t2[r * KK + k] = o2;
        else       g_t02[k]         = o2;
    }
}

// ---------------------------------------------------------------------------
// Kernel B: main edge kernel. 512 blocks; block handles 2 consecutive i-rows
// of one batch b (single full wave at ~5 blocks/SM -> no tail wave; the
// 512-row shared pos/flag tile is loaded once for both rows).
// Per row: 8 warps, warp w owns j in [w*64,(w+1)*64) in two 32-wide chunks:
//   - scalar phase lane-parallel over j (dist, 1/dist, x = mul*dist+bias)
//   - broadcast phase: per j, each lane computes 4 contiguous k, stores float4
//     with a warp-UNIFORM branch that skips all math for padded j (store zeros)
// ---------------------------------------------------------------------------
__global__ __launch_bounds__(256) void edge_kernel(
        const float* __restrict__ pos,
        const int*   __restrict__ nte,
        const int*   __restrict__ pad,
        const int*   __restrict__ maa,
        const int*   __restrict__ mpos,
        const float* __restrict__ mul_w,
        const float* __restrict__ bias_w,
        float* __restrict__ ef,
        float* __restrict__ dp) {
    const int b  = blockIdx.x >> 8;            // 512 blocks: b = hi bit
    const int i0 = (blockIdx.x & 255) * 2;     // 2 rows per block
    const int tid = threadIdx.x, wid = tid >> 5, lid = tid & 31;

    __shared__ float spx[NN], spy[NN], spz[NN];
    __shared__ int   sfl[NN];
    __shared__ float sred[KK];

    for (int idx = tid; idx < NN; idx += 256) {
        int g = b * NN + idx;
        spx[idx] = pos[g * 3 + 0];
        spy[idx] = pos[g * 3 + 1];
        spz[idx] = pos[g * 3 + 2];
        sfl[idx] = (pad[g] ? 1 : 0) | (mpos[g] ? 2 : 0) | (maa[g] ? 4 : 0);
    }

    // per-lane gaussian constants for k = 4*lid .. 4*lid+3 (b-dependent tv4)
    const float4 mk4 = *(const float4*)&g_mk[4 * lid];
    const float4 k4  = *(const float4*)&g_k1[4 * lid];
    const float4 c4  = *(const float4*)&g_coef[4 * lid];
    const float4 tv4 = *(const float4*)&g_t2[b * KK + 4 * lid];
    const float4 t04 = *(const float4*)&g_t02[4 * lid];

    const int2* ntep = (const int2*)nte;

    for (int ii = 0; ii < 2; ii++) {
        const int i = i0 + ii;
        if (tid < KK) sred[tid] = 0.0f;
        __syncthreads();

        const float pix = spx[i], piy = spy[i], piz = spz[i];
        const int fi = sfl[i];
        const bool maa_i = (fi & 4) != 0;
        const bool mp_i  = (fi & 2) != 0;
        const size_t row = (size_t)(b * NN + i) * NN;

        float a0 = 0.f, a1 = 0.f, a2 = 0.f, a3 = 0.f;

        for (int jb = wid * 64; jb < wid * 64 + 64; jb += 32) {
            const int j = jb + lid;
            // ---- scalar phase (lane-parallel over j) ----
            float dx = spx[j] - pix, dy = spy[j] - piy, dz = spz[j] - piz;
            float d2 = fmaf(dx, dx, fmaf(dy, dy, dz * dz));
            float dist = __fsqrt_rn(d2);
            float inv = __fdividef(1.0f, dist + 1e-5f);
            size_t dpb = (row + j) * 3;
            __stcs(dp + dpb + 0, dx * inv);
            __stcs(dp + dpb + 1, dy * inv);
            __stcs(dp + dpb + 2, dz * inv);

            int2 v = __ldg(&ntep[row + j]);
            int f = sfl[j];
            int e0 = maa_i    ? 0 : v.x;
            int e1 = (f & 4)  ? 0 : v.y;
            float mul = __ldg(&mul_w[e0])  + __ldg(&mul_w[e1]);
            float bia = __ldg(&bias_w[e0]) + __ldg(&bias_w[e1]);
            float x = fmaf(mul, dist, bia);

            unsigned pmask = __ballot_sync(0xffffffffu, (f & 1) != 0);
            unsigned smask = __ballot_sync(0xffffffffu, mp_i || ((f & 2) != 0));

            // ---- broadcast phase: per j, 128 k across warp ----
            #pragma unroll 4
            for (int t = 0; t < 32; t++) {
                float xt = __shfl_sync(0xffffffffu, x, t);
                float4* op = (float4*)(ef + (row + jb + t) * KK) + lid;
                if ((pmask >> t) & 1u) {           // warp-uniform: padded j
                    __stcs(op, make_float4(0.f, 0.f, 0.f, 0.f));
                } else {
                    const bool sel = (smask >> t) & 1u;
                    float u0 = fmaf(xt, k4.x, -mk4.x);
                    float u1 = fmaf(xt, k4.y, -mk4.y);
                    float u2 = fmaf(xt, k4.z, -mk4.z);
                    float u3 = fmaf(xt, k4.w, -mk4.w);
                    float v0 = fmaf(c4.x, ex2f(-u0 * u0), sel ? tv4.x : t04.x);
                    float v1 = fmaf(c4.y, ex2f(-u1 * u1), sel ? tv4.y : t04.y);
                    float v2 = fmaf(c4.z, ex2f(-u2 * u2), sel ? tv4.z : t04.z);
                    float v3 = fmaf(c4.w, ex2f(-u3 * u3), sel ? tv4.w : t04.w);
                    a0 += v0; a1 += v1; a2 += v2; a3 += v3;
                    __stcs(op, make_float4(v0, v1, v2, v3));
                }
            }
        }

        atomicAdd(&sred[4 * lid + 0], a0);
        atomicAdd(&sred[4 * lid + 1], a1);
        atomicAdd(&sred[4 * lid + 2], a2);
        atomicAdd(&sred[4 * lid + 3], a3);
        __syncthreads();
        if (tid < KK) g_sum[(size_t)(b * NN + i) * KK + tid] = sred[tid];
        __syncthreads();
    }
}

// ---------------------------------------------------------------------------
// Kernel C: merge = sum_edge @ proj_w + proj_b, zero padded i-rows.
// grid = (128 row-blocks) x (3 E-slices). Each block: 8 rows x 256 E-cols.
// smem: st[k] = {rows 0..3, rows 4..7} as two float4 (16B-aligned ->
// broadcast LDS.128). Inner loop per k: 1 LDG + 2 LDS.128 + 8 FMA, unroll 8.
// ---------------------------------------------------------------------------
__global__ __launch_bounds__(256) void proj_kernel(
        const float* __restrict__ W,
        const float* __restrict__ bias,
        const int*   __restrict__ pad,
        float* __restrict__ merge) {
    const int r0 = blockIdx.x * 8;
    const int e0 = blockIdx.y * 256 + threadIdx.x;
    __shared__ float4 st[KK][2];     // st[k][0] = rows 0-3, st[k][1] = rows 4-7
    for (int idx = threadIdx.x; idx < 8 * KK; idx += 256) {
        int r = idx >> 7, k = idx & (KK - 1);     // coalesced g_sum read
        ((float*)st)[k * 8 + r] = g_sum[(r0 + r) * KK + k];
    }
    __syncthreads();

    float acc[8];
    #pragma unroll
    for (int r = 0; r < 8; r++) acc[r] = 0.f;

    #pragma unroll 8
    for (int k = 0; k < KK; k++) {
        float w0 = __ldg(&W[k * EE + e0]);
        float4 s0 = st[k][0];
        float4 s1 = st[k][1];
        acc[0] = fmaf(s0.x, w0, acc[0]);
        acc[1] = fmaf(s0.y, w0, acc[1]);
        acc[2] = fmaf(s0.z, w0, acc[2]);
        acc[3] = fmaf(s0.w, w0, acc[3]);
        acc[4] = fmaf(s1.x, w0, acc[4]);
        acc[5] = fmaf(s1.y, w0, acc[5]);
        acc[6] = fmaf(s1.z, w0, acc[6]);
        acc[7] = fmaf(s1.w, w0, acc[7]);
    }
    float b0 = __ldg(&bias[e0]);
    #pragma unroll
    for (int r = 0; r < 8; r++) {
        int rr = r0 + r;
        bool p = pad[rr] != 0;
        merge[(size_t)rr * EE + e0] = p ? 0.f : acc[r] + b0;
    }
}

// ---------------------------------------------------------------------------
extern "C" void kernel_launch(void* const* d_in, const int* in_sizes, int n_in,
                              void* d_out, int out_size) {
    const float* pos    = (const float*)d_in[0];
    const int*   nte    = (const int*)  d_in[1];
    const int*   pad    = (const int*)  d_in[2];
    const int*   maa    = (const int*)  d_in[3];
    const int*   mpos   = (const int*)  d_in[4];
    const int*   tpos   = (const int*)  d_in[5];
    const float* means  = (const float*)d_in[6];
    const float* stds   = (const float*)d_in[7];
    const float* mul_w  = (const float*)d_in[8];
    const float* bias_w = (const float*)d_in[9];
    const float* proj_w = (const float*)d_in[10];
    const float* proj_b = (const float*)d_in[11];
    const float* t_w1   = (const float*)d_in[12];
    const float* t_b1   = (const float*)d_in[13];
    const float* t_w2   = (const float*)d_in[14];
    const float* t_b2   = (const float*)d_in[15];
    float* out = (float*)d_out;

    prep1<<<12, 1024>>>(t_w1, t_b1, tpos);
    prep2<<<12, 1024>>>(t_w2, t_b2, means, stds);
    edge_kernel<<<BB * NN / 2, 256>>>(pos, nte, pad, maa, mpos, mul_w, bias_w,
                                      out, out + DP_OFF);
    proj_kernel<<<dim3((BB * NN) / 8, 3), 256>>>(proj_w, proj_b, pad, out + MERGE_OFF);
}

// round 13
// speedup vs baseline: 1.1985x; 1.0210x over previous
#include <cuda_runtime.h>
#include <cstdint>
#include <cstddef>

// Problem constants
#define BB 2
#define NN 512
#define KK 128
#define EE 768

// Output layout (concatenated, fp32): edge_feature | merge | delta_pos
static const size_t EF_ELEMS  = (size_t)BB * NN * NN * KK;   // 67,108,864
static const size_t MERGE_OFF = EF_ELEMS;                    // 67,108,864
static const size_t DP_OFF    = EF_ELEMS + (size_t)BB*NN*EE; // 67,895,296

// Scratch (device globals only — no allocation allowed)
__device__ __align__(16) float g_mk[KK];    // means * k1  (for u = fma(x, k1, -mk))
__device__ __align__(16) float g_k1[KK];    // (1/(|std|+0.01)) * sqrt(0.5*log2(e))
__device__ __align__(16) float g_coef[KK];  // (1/(|std|+0.01)) / sqrt(2*PI)
__device__ __align__(16) float g_t2[BB * KK];   // 2 * t_enc(time_pos[b])
__device__ __align__(16) float g_t02[KK];       // 2 * t_enc(0)
__device__ __align__(16) float g_h[3 * KK];     // hidden after SiLU

__device__ __forceinline__ float ex2f(float x) {
    float r; asm("ex2.approx.ftz.f32 %0, %1;" : "=f"(r) : "f"(x)); return r;
}

// ---------------------------------------------------------------------------
// Kernel P1: layer-1 of timestep MLP. 12 blocks x 1024 thr = 384 warps,
// one warp per output (r,k); r in {t0, t1, 0}, k in [0,128).
// Each lane computes its 4 sinusoidal-embedding values inline,
// loads 4 W1 elements (independent -> single latency round), shfl-reduce.
// ---------------------------------------------------------------------------
__global__ __launch_bounds__(1024) void prep1(const float* __restrict__ W1,
                                              const float* __restrict__ b1,
                                              const int*   __restrict__ tpos) {
    const int w = blockIdx.x * 32 + (threadIdx.x >> 5);   // 0..383
    const int l = threadIdx.x & 31;
    const int r = w >> 7, k = w & (KK - 1);
    const float t = (r < 2) ? (float)__ldg(&tpos[r]) : 0.0f;

    float s = 0.0f;
    #pragma unroll
    for (int sgl = 0; sgl < 4; sgl++) {
        int j = l + 32 * sgl;
        int h = (j < 64) ? j : (j - 64);
        float freq = expf(-9.210340371976184f * (float)h / 64.0f);
        float arg = t * freq;
        float e = (j < 64) ? cosf(arg) : sinf(arg);
        s = fmaf(e, __ldg(&W1[j * KK + k]), s);
    }
    #pragma unroll
    for (int o = 16; o > 0; o >>= 1) s += __shfl_xor_sync(0xffffffffu, s, o);
    if (l == 0) {
        float hv = s + __ldg(&b1[k]);
        hv = hv / (1.0f + expf(-hv));     // SiLU
        g_h[r * KK + k] = hv;
    }
}

// ---------------------------------------------------------------------------
// Kernel P2: layer-2 of timestep MLP (same shape) + gaussian constants.
// ---------------------------------------------------------------------------
__global__ __launch_bounds__(1024) void prep2(const float* __restrict__ W2,
                                              const float* __restrict__ b2,
                                              const float* __restrict__ means,
                                              const float* __restrict__ stds) {
    if (blockIdx.x == 0 && threadIdx.x < KK) {
        const int k = threadIdx.x;
        float sd = fabsf(__ldg(&stds[k])) + 0.01f;
        float is = 1.0f / sd;
        float k1 = is * 0.8493218002880191f;                // sqrt(0.5 * log2(e))
        g_k1[k]   = k1;
        g_mk[k]   = __ldg(&means[k]) * k1;
        g_coef[k] = is * (1.0f / sqrtf(2.0f * 3.14159f));   // ref's PI constant
    }
    const int w = blockIdx.x * 32 + (threadIdx.x >> 5);
    const int l = threadIdx.x & 31;
    const int r = w >> 7, k = w & (KK - 1);
    float s = 0.0f;
    #pragma unroll
    for (int sgl = 0; sgl < 4; sgl++) {
        int j = l + 32 * sgl;
        s = fmaf(__ldg(&g_h[r * KK + j]), __ldg(&W2[j * KK + k]), s);
    }
    #pragma unroll
    for (int o = 16; o > 0; o >>= 1) s += __shfl_xor_sync(0xffffffffu, s, o);
    if (l == 0) {
        float o2 = 2.0f * (s + __ldg(&b2[k]));
        if (r < 2) g_t2[r * KK + k] = o2;
        else       g_t02[k]         = o2;
    }
}

// ---------------------------------------------------------------------------
// Kernel B (fused edge + projection): 512 blocks; block handles 2 consecutive
// i-rows of one batch b. Per row:
//   - 8 warps compute edge_feature for all j (store float4, accumulate sum)
//   - shared reduction -> sred4[32] (float4-aligned)
//   - SAME threads project: merge[b,i,e] = sum . W[:,e] + bias[e]
//     (thread handles e = tid, tid+256, tid+512; W reads L2-resident;
//      sred consumed 4 k per step via broadcast LDS.128)
// No g_sum global scratch, no separate proj kernel.
// ---------------------------------------------------------------------------
__global__ __launch_bounds__(256) void edge_kernel(
        const float* __restrict__ pos,
        const int*   __restrict__ nte,
        const int*   __restrict__ pad,
        const int*   __restrict__ maa,
        const int*   __restrict__ mpos,
        const float* __restrict__ mul_w,
        const float* __restrict__ bias_w,
        const float* __restrict__ projW,
        const float* __restrict__ projB,
        float* __restrict__ ef,
        float* __restrict__ merge,
        float* __restrict__ dp) {
    const int b  = blockIdx.x >> 8;            // 512 blocks: b = hi bit
    const int i0 = (blockIdx.x & 255) * 2;     // 2 rows per block
    const int tid = threadIdx.x, wid = tid >> 5, lid = tid & 31;

    __shared__ float  spx[NN], spy[NN], spz[NN];
    __shared__ int    sfl[NN];
    __shared__ float4 sred4[KK / 4];           // 16B-aligned block reduction
    float* sred = (float*)sred4;

    for (int idx = tid; idx < NN; idx += 256) {
        int g = b * NN + idx;
        spx[idx] = pos[g * 3 + 0];
        spy[idx] = pos[g * 3 + 1];
        spz[idx] = pos[g * 3 + 2];
        sfl[idx] = (pad[g] ? 1 : 0) | (mpos[g] ? 2 : 0) | (maa[g] ? 4 : 0);
    }

    // per-lane gaussian constants for k = 4*lid .. 4*lid+3 (b-dependent tv4)
    const float4 mk4 = *(const float4*)&g_mk[4 * lid];
    const float4 k4  = *(const float4*)&g_k1[4 * lid];
    const float4 c4  = *(const float4*)&g_coef[4 * lid];
    const float4 tv4 = *(const float4*)&g_t2[b * KK + 4 * lid];
    const float4 t04 = *(const float4*)&g_t02[4 * lid];

    const int2* ntep = (const int2*)nte;

    for (int ii = 0; ii < 2; ii++) {
        const int i = i0 + ii;
        if (tid < KK) sred[tid] = 0.0f;
        __syncthreads();

        const float pix = spx[i], piy = spy[i], piz = spz[i];
        const int fi = sfl[i];
        const bool maa_i = (fi & 4) != 0;
        const bool mp_i  = (fi & 2) != 0;
        const size_t row = (size_t)(b * NN + i) * NN;

        float a0 = 0.f, a1 = 0.f, a2 = 0.f, a3 = 0.f;

        for (int jb = wid * 64; jb < wid * 64 + 64; jb += 32) {
            const int j = jb + lid;
            // ---- scalar phase (lane-parallel over j) ----
            float dx = spx[j] - pix, dy = spy[j] - piy, dz = spz[j] - piz;
            float d2 = fmaf(dx, dx, fmaf(dy, dy, dz * dz));
            float dist = __fsqrt_rn(d2);
            float inv = __fdividef(1.0f, dist + 1e-5f);
            size_t dpb = (row + j) * 3;
            __stcs(dp + dpb + 0, dx * inv);
            __stcs(dp + dpb + 1, dy * inv);
            __stcs(dp + dpb + 2, dz * inv);

            int2 v = __ldg(&ntep[row + j]);
            int f = sfl[j];
            int e0 = maa_i    ? 0 : v.x;
            int e1 = (f & 4)  ? 0 : v.y;
            float mul = __ldg(&mul_w[e0])  + __ldg(&mul_w[e1]);
            float bia = __ldg(&bias_w[e0]) + __ldg(&bias_w[e1]);
            float x = fmaf(mul, dist, bia);

            unsigned pmask = __ballot_sync(0xffffffffu, (f & 1) != 0);
            unsigned smask = __ballot_sync(0xffffffffu, mp_i || ((f & 2) != 0));

            // ---- broadcast phase: per j, 128 k across warp ----
            #pragma unroll 4
            for (int t = 0; t < 32; t++) {
                float xt = __shfl_sync(0xffffffffu, x, t);
                float4* op = (float4*)(ef + (row + jb + t) * KK) + lid;
                if ((pmask >> t) & 1u) {           // warp-uniform: padded j
                    __stcs(op, make_float4(0.f, 0.f, 0.f, 0.f));
                } else {
                    const bool sel = (smask >> t) & 1u;
                    float u0 = fmaf(xt, k4.x, -mk4.x);
                    float u1 = fmaf(xt, k4.y, -mk4.y);
                    float u2 = fmaf(xt, k4.z, -mk4.z);
                    float u3 = fmaf(xt, k4.w, -mk4.w);
                    float v0 = fmaf(c4.x, ex2f(-u0 * u0), sel ? tv4.x : t04.x);
                    float v1 = fmaf(c4.y, ex2f(-u1 * u1), sel ? tv4.y : t04.y);
                    float v2 = fmaf(c4.z, ex2f(-u2 * u2), sel ? tv4.z : t04.z);
                    float v3 = fmaf(c4.w, ex2f(-u3 * u3), sel ? tv4.w : t04.w);
                    a0 += v0; a1 += v1; a2 += v2; a3 += v3;
                    __stcs(op, make_float4(v0, v1, v2, v3));
                }
            }
        }

        atomicAdd(&sred[4 * lid + 0], a0);
        atomicAdd(&sred[4 * lid + 1], a1);
        atomicAdd(&sred[4 * lid + 2], a2);
        atomicAdd(&sred[4 * lid + 3], a3);
        __syncthreads();

        // ---- fused projection for row i: merge = sred . W + bias ----
        {
            const size_t mb = (size_t)(b * NN + i) * EE;
            if (fi & 1) {                         // padded i-row -> zeros
                __stcs(merge + mb + tid,        0.0f);
                __stcs(merge + mb + tid + 256,  0.0f);
                __stcs(merge + mb + tid + 512,  0.0f);
            } else {
                float acc0 = 0.f, acc1 = 0.f, acc2 = 0.f;
                #pragma unroll 4
                for (int kq = 0; kq < KK / 4; kq++) {
                    float4 s4 = sred4[kq];         // broadcast LDS.128
                    int k = 4 * kq;
                    acc0 = fmaf(s4.x, __ldg(&projW[(k+0) * EE + tid      ]), acc0);
                    acc1 = fmaf(s4.x, __ldg(&projW[(k+0) * EE + tid + 256]), acc1);
                    acc2 = fmaf(s4.x, __ldg(&projW[(k+0) * EE + tid + 512]), acc2);
                    acc0 = fmaf(s4.y, __ldg(&projW[(k+1) * EE + tid      ]), acc0);
                    acc1 = fmaf(s4.y, __ldg(&projW[(k+1) * EE + tid + 256]), acc1);
                    acc2 = fmaf(s4.y, __ldg(&projW[(k+1) * EE + tid + 512]), acc2);
                    acc0 = fmaf(s4.z, __ldg(&projW[(k+2) * EE + tid      ]), acc0);
                    acc1 = fmaf(s4.z, __ldg(&projW[(k+2) * EE + tid + 256]), acc1);
                    acc2 = fmaf(s4.z, __ldg(&projW[(k+2) * EE + tid + 512]), acc2);
                    acc0 = fmaf(s4.w, __ldg(&projW[(k+3) * EE + tid      ]), acc0);
                    acc1 = fmaf(s4.w, __ldg(&projW[(k+3) * EE + tid + 256]), acc1);
                    acc2 = fmaf(s4.w, __ldg(&projW[(k+3) * EE + tid + 512]), acc2);
                }
                __stcs(merge + mb + tid,       acc0 + __ldg(&projB[tid]));
                __stcs(merge + mb + tid + 256, acc1 + __ldg(&projB[tid + 256]));
                __stcs(merge + mb + tid + 512, acc2 + __ldg(&projB[tid + 512]));
            }
        }
        __syncthreads();   // all reads of sred done before next row zeroes it
    }
}

// ---------------------------------------------------------------------------
extern "C" void kernel_launch(void* const* d_in, const int* in_sizes, int n_in,
                              void* d_out, int out_size) {
    const float* pos    = (const float*)d_in[0];
    const int*   nte    = (const int*)  d_in[1];
    const int*   pad    = (const int*)  d_in[2];
    const int*   maa    = (const int*)  d_in[3];
    const int*   mpos   = (const int*)  d_in[4];
    const int*   tpos   = (const int*)  d_in[5];
    const float* means  = (const float*)d_in[6];
    const float* stds   = (const float*)d_in[7];
    const float* mul_w  = (const float*)d_in[8];
    const float* bias_w = (const float*)d_in[9];
    const float* proj_w = (const float*)d_in[10];
    const float* proj_b = (const float*)d_in[11];
    const float* t_w1   = (const float*)d_in[12];
    const float* t_b1   = (const float*)d_in[13];
    const float* t_w2   = (const float*)d_in[14];
    const float* t_b2   = (const float*)d_in[15];
    float* out = (float*)d_out;

    prep1<<<12, 1024>>>(t_w1, t_b1, tpos);
    prep2<<<12, 1024>>>(t_w2, t_b2, means, stds);
    edge_kernel<<<BB * NN / 2, 256>>>(pos, nte, pad, maa, mpos, mul_w, bias_w,
                                      proj_w, proj_b,
                                      out, out + MERGE_OFF, out + DP_OFF);
}